// round 9
// baseline (speedup 1.0000x reference)
#include <cuda_runtime.h>
#include <stdint.h>

// jax_threefry_partitionable=True semantics (verified rel_err==0 in rounds 1-8)

#define NCAP      20480            // max faces supported by smem table / bitset
#define VIS_WORDS 640              // NCAP/32 bitset words per walk
#define TCAP      64               // L+1 iterations precomputed
#define THREADS   256

// shared-memory layout (u32 word offsets)
#define OFF_VIS   0                         // u32 vis[640][32]
#define OFF_SEQ   (OFF_VIS + VIS_WORDS*32)  // int seq[64][32]
#define OFF_RND   (OFF_SEQ + TCAP*32)       // u32 rnd[64][32]
#define OFF_RINGX (OFF_RND + TCAP*32)       // u32 ringx[2][8][32]
#define OFF_RINGY (OFF_RINGX + 512)         // u32 ringy[2][8][32]
#define OFF_P01   (OFF_RINGY + 512)         // u32 p01[NCAP]   (n0 | n1<<16)
#define OFF_N2    (OFF_P01 + NCAP)          // u16 n2[NCAP] -> NCAP/2 words
#define OFF_CXYZ  (OFF_N2 + NCAP/2)         // float cxyz[32][3]
#define SMEM_WORDS (OFF_CXYZ + 96 + 4)
#define SMEM_BYTES (SMEM_WORDS * 4)         // 225,680 B < 232,448 B sm_103a limit

struct U2 { uint32_t x, y; };

// Threefry-2x32, 20 rounds — exact JAX/Random123 schedule.
__device__ __forceinline__ U2 tf(uint32_t k0, uint32_t k1, uint32_t x0, uint32_t x1) {
    uint32_t ks2 = k0 ^ k1 ^ 0x1BD11BDAu;
    x0 += k0; x1 += k1;
#define TF_R(r) { x0 += x1; x1 = __funnelshift_l(x1, x1, (r)); x1 ^= x0; }
    TF_R(13) TF_R(15) TF_R(26) TF_R(6)
    x0 += k1;  x1 += ks2 + 1u;
    TF_R(17) TF_R(29) TF_R(16) TF_R(24)
    x0 += ks2; x1 += k0 + 2u;
    TF_R(13) TF_R(15) TF_R(26) TF_R(6)
    x0 += k0;  x1 += k1 + 3u;
    TF_R(17) TF_R(29) TF_R(16) TF_R(24)
    x0 += k1;  x1 += ks2 + 4u;
    TF_R(13) TF_R(15) TF_R(26) TF_R(6)
    x0 += ks2; x1 += k0 + 5u;
#undef TF_R
    U2 o; o.x = x0; o.y = x1; return o;
}

__device__ __forceinline__ uint32_t tf_bits(U2 k) {          // random_bits(key,32,())
    U2 o = tf(k.x, k.y, 0u, 0u);
    return o.x ^ o.y;
}
__device__ __forceinline__ uint32_t jrandint(U2 k, uint32_t span) { // randint(k,(),0,span)
    U2 ka = tf(k.x, k.y, 0u, 0u);
    U2 kb = tf(k.x, k.y, 0u, 1u);
    uint32_t h = tf_bits(ka), l = tf_bits(kb);
    uint32_t m = 65536u % span; m = (m * m) % span;
    return ((h % span) * m + (l % span)) % span;
}

// packed per-iteration draw: r2 | r3<<8 (spans 2 and 3, pre-reduced)
__device__ __forceinline__ uint32_t rand_draw(U2 k) {
    U2 k1 = tf(k.x, k.y, 0u, 1u);          // split4[1]
    U2 ka = tf(k1.x, k1.y, 0u, 0u);        // split2(k1)
    U2 kb = tf(k1.x, k1.y, 0u, 1u);
    const uint32_t h = tf_bits(ka), l = tf_bits(kb);
    return (l & 1u) | (((((h % 3u) + (l % 3u)) % 3u)) << 8);
}

// Walk state (warp 1, one walk per lane)
struct WalkState { int i, bs, it, cur; };

__device__ __forceinline__ void walk_advance(
    WalkState& st, int itlim, int L, int lane, int wid, int N,
    bool use_smem, const int* __restrict__ nbb,
    uint32_t* __restrict__ vis, int* __restrict__ seq,
    const uint32_t* __restrict__ rnd,
    const uint32_t* __restrict__ p01s, const uint16_t* __restrict__ n2s)
{
    int i = st.i, bs = st.bs, it = st.it, cur = st.cur;
    while (i <= L && it < itlim) {
        const uint32_t rp = (it < TCAP) ? rnd[it * 32 + lane] : 0u;
        int n0, n1, n2;
        if (use_smem) {
            const uint32_t p = p01s[cur];
            n0 = (int)(p & 0xFFFFu);
            n1 = (int)(p >> 16);
            n2 = (int)n2s[cur];
        } else {
            n0 = __ldg(nbb + 3 * cur);
            n1 = __ldg(nbb + 3 * cur + 1);
            n2 = __ldg(nbb + 3 * cur + 2);
        }

        const int u0 = ((vis[(n0 >> 5) * 32 + lane] >> (n0 & 31)) & 1u) ? 0 : 1;
        const int u1 = ((vis[(n1 >> 5) * 32 + lane] >> (n1 & 31)) & 1u) ? 0 : 1;
        const int u2 = ((vis[(n2 >> 5) * 32 + lane] >> (n2 & 31)) & 1u) ? 0 : 1;
        const int cnt = u0 + u1 + u2;

        if (cnt > 0 && it < TCAP) {
            const uint32_t r = (cnt == 3) ? ((rp >> 8) & 3u)
                             : (cnt == 2) ? (rp & 1u) : 0u;
            const int t = (int)r + 1;
            const int ta = (u0 == t) ? n0 : ((u0 + u1 == t) ? n1 : n2);
            seq[i * 32 + lane] = ta;
            vis[(ta >> 5) * 32 + lane] |= 1u << (ta & 31);
            cur = ta; bs = 1; ++i;
        } else {
            // slow path — recompute chain key for iteration `it` from base key
            U2 kc = tf(0u, 42u, 0u, (uint32_t)wid);
            #pragma unroll 1
            for (int j = 0; j < it; ++j) kc = tf(kc.x, kc.y, 0u, 0u);
            if (cnt > 0) {
                U2 k1 = tf(kc.x, kc.y, 0u, 1u);
                const int t = (int)jrandint(k1, (uint32_t)cnt) + 1;
                const int ta = (u0 == t) ? n0 : ((u0 + u1 == t) ? n1 : n2);
                seq[i * 32 + lane] = ta;
                vis[(ta >> 5) * 32 + lane] |= 1u << (ta & 31);
                cur = ta; bs = 1; ++i;
            } else {
                U2 k2 = tf(kc.x, kc.y, 0u, 2u);
                U2 k3 = tf(kc.x, kc.y, 0u, 3u);
                int bsc = bs, found = 0, ta = 0;
                U2 kk = k2;
                #pragma unroll 1
                while (!found && i > bsc) {
                    U2 kkn = tf(kk.x, kk.y, 0u, 0u);
                    U2 kp  = tf(kk.x, kk.y, 0u, 1u);
                    const int back = seq[(i - bsc - 1) * 32 + lane];
                    const int b0 = __ldg(nbb + 3 * back);
                    const int b1 = __ldg(nbb + 3 * back + 1);
                    const int b2 = __ldg(nbb + 3 * back + 2);
                    const int m0 = ((vis[(b0 >> 5) * 32 + lane] >> (b0 & 31)) & 1u) ? 0 : 1;
                    const int m1 = ((vis[(b1 >> 5) * 32 + lane] >> (b1 & 31)) & 1u) ? 0 : 1;
                    const int m2 = ((vis[(b2 >> 5) * 32 + lane] >> (b2 & 31)) & 1u) ? 0 : 1;
                    const int bc = m0 + m1 + m2;
                    if (bc > 0) {
                        found = 1;
                        const int t = (int)jrandint(kp, (uint32_t)bc) + 1;
                        ta = (m0 == t) ? b0 : ((m0 + m1 == t) ? b1 : b2);
                    } else {
                        bsc += 2;
                    }
                    kk = kkn;
                }
                if (found) {
                    const int inew = i - bsc;
                    for (int j = inew; j < i; ++j) seq[j * 32 + lane] = ta;
                    vis[(ta >> 5) * 32 + lane] |= 1u << (ta & 31);
                    cur = ta; bs = bsc; i = inew + 1;
                } else {
                    const int ta2 = (int)jrandint(k3, (uint32_t)N);
                    seq[i * 32 + lane] = ta2;
                    vis[(ta2 >> 5) * 32 + lane] |= 1u << (ta2 & 31);
                    cur = ta2; bs = 1; ++i;
                }
            }
        }
        ++it;
    }
    st.i = i; st.bs = bs; st.it = it; st.cur = cur;
}

__global__ void __launch_bounds__(THREADS, 1)
fused_walk_kernel(const float* __restrict__ xyz,
                  const int*   __restrict__ nbrs,
                  const int*   __restrict__ centers,
                  const int*   __restrict__ pN,
                  float*       __restrict__ out,
                  int xyz_total, int walks, int L)
{
    extern __shared__ uint32_t sm[];
    uint32_t* vis   = sm + OFF_VIS;
    int*      seq   = (int*)(sm + OFF_SEQ);
    uint32_t* rnd   = sm + OFF_RND;
    uint32_t* ringx = sm + OFF_RINGX;
    uint32_t* ringy = sm + OFF_RINGY;
    uint32_t* p01s  = sm + OFF_P01;
    uint16_t* n2s   = (uint16_t*)(sm + OFF_N2);
    float*    cxyz  = (float*)(sm + OFF_CXYZ);

    const int tid  = threadIdx.x;
    const int lane = tid & 31;
    const int warp = tid >> 5;
    const int blk0 = blockIdx.x * 32;

    const int N = *pN;
    const int B = xyz_total / (3 * N);
    const int G = walks / B;
    const bool use_smem = (N <= NCAP) && (G % 32 == 0);
    const int  pb  = (blk0 < walks) ? (blk0 / G) : 0;
    const int* __restrict__ btab = nbrs + (long long)pb * N * 3;
    const bool valid = (blk0 + lane < walks);

    // ── Phase 0: clear bitset; warp 7 does per-walk init ──
    #pragma unroll 8
    for (int i = tid; i < VIS_WORDS * 32; i += THREADS) vis[i] = 0u;
    if (warp == 7 && valid) {
        const int wg = blk0 + lane;
        const int bb = wg / G;
        const float* __restrict__ xb = xyz + (long long)bb * N * 3;
        const int f0 = __ldg(centers + wg);
        cxyz[lane * 3]     = __ldg(xb + 3 * f0);
        cxyz[lane * 3 + 1] = __ldg(xb + 3 * f0 + 1);
        cxyz[lane * 3 + 2] = __ldg(xb + 3 * f0 + 2);
        seq[lane] = f0;
        vis[(f0 >> 5) * 32 + lane] |= 1u << (f0 & 31);
    }
    __syncthreads();

    // ── Pipelined epochs s=0..8:
    //    warp 0:      chain epoch s (s<8)
    //    warps 1-7:   table pack, thirds, epochs 0-2
    //    warps 2-7:   rand for epoch s-1 (s>=1), 2-task ILP jam
    //    warp 1:      walk from s=3, safe limit it < 8(s-1)
    U2 kreg;
    if (warp == 0 && valid)
        kreg = tf(0u, 42u, 0u, (uint32_t)(blk0 + lane));   // split(key(42), walks)[wid]

    const int wid1 = blk0 + lane;
    const int* __restrict__ nbb1 = nbrs + (long long)(valid ? wid1 / G : 0) * N * 3;
    WalkState st; st.i = 1; st.bs = 1; st.it = 0; st.cur = (warp == 1 && valid) ? seq[lane] : 0;

    const int ngroups = use_smem ? ((N + 3) >> 2) : 0;
    const int chunk   = (ngroups + 2) / 3;                 // pack third per epoch

    for (int s = 0; s <= 8; ++s) {
        if (warp == 0) {
            if (s < 8 && valid) {
                const int slot = (s & 1) * 256;
                #pragma unroll
                for (int j = 0; j < 8; ++j) {
                    ringx[slot + j * 32 + lane] = kreg.x;
                    ringy[slot + j * 32 + lane] = kreg.y;
                    kreg = tf(kreg.x, kreg.y, 0u, 0u);     // knew = split4[0]
                }
            }
        } else {
            // table pack: thirds over epochs 0..2, warps 1-7 (224 workers)
            if (use_smem && s <= 2) {
                const int4* __restrict__ tbl4 = (const int4*)btab;
                const int gend = min(chunk * (s + 1), ngroups);
                #pragma unroll 1
                for (int g = chunk * s + (tid - 32); g < gend; g += 224) {
                    const int f = g * 4;
                    if (f + 3 < N) {
                        const int4 a = __ldg(tbl4 + 3 * g);
                        const int4 b = __ldg(tbl4 + 3 * g + 1);
                        const int4 c = __ldg(tbl4 + 3 * g + 2);
                        p01s[f]     = (uint32_t)a.x | ((uint32_t)a.y << 16);
                        n2s [f]     = (uint16_t)a.z;
                        p01s[f + 1] = (uint32_t)a.w | ((uint32_t)b.x << 16);
                        n2s [f + 1] = (uint16_t)b.y;
                        p01s[f + 2] = (uint32_t)b.z | ((uint32_t)b.w << 16);
                        n2s [f + 2] = (uint16_t)c.x;
                        p01s[f + 3] = (uint32_t)c.y | ((uint32_t)c.z << 16);
                        n2s [f + 3] = (uint16_t)c.w;
                    } else {
                        #pragma unroll 1
                        for (int ff = f; ff < N; ++ff) {
                            const int x0 = __ldg(btab + 3 * ff);
                            const int x1 = __ldg(btab + 3 * ff + 1);
                            const int x2 = __ldg(btab + 3 * ff + 2);
                            p01s[ff] = (uint32_t)x0 | ((uint32_t)x1 << 16);
                            n2s [ff] = (uint16_t)x2;
                        }
                    }
                }
            }
            // rand for epoch s-1: 256 tasks / 192 workers, two tasks jammed for ILP
            if (s >= 1 && warp >= 2) {
                const int slot = ((s - 1) & 1) * 256;
                const int j0 = tid - 64;                   // 0..191
                const int j1 = j0 + 192;                   // 192..383 (valid if <256)
                const int tA = (s - 1) * 8 + (j0 >> 5), wA = j0 & 31;
                const int tB = (s - 1) * 8 + (j1 >> 5), wB = j1 & 31;
                const bool doA = (blk0 + wA < walks);
                const bool doB = (j1 < 256) && (blk0 + wB < walks);
                U2 kA, kB;
                kA.x = ringx[slot + (tA & 7) * 32 + wA];
                kA.y = ringy[slot + (tA & 7) * 32 + wA];
                if (doB) { kB.x = ringx[slot + (tB & 7) * 32 + wB];
                           kB.y = ringy[slot + (tB & 7) * 32 + wB]; }
                else     { kB.x = 0u; kB.y = 0u; }
                // two independent depth-3 chains — compiler interleaves them
                const uint32_t vA = rand_draw(kA);
                const uint32_t vB = rand_draw(kB);
                if (doA) rnd[tA * 32 + wA] = vA;
                if (doB) rnd[tB * 32 + wB] = vB;
            }
            // pipelined walk (warp 1, epochs 3..8): safe limit it < 8(s-1)
            if (warp == 1 && s >= 3 && valid) {
                int lim = 8 * (s - 1); if (lim > TCAP) lim = TCAP;
                walk_advance(st, lim, L, lane, wid1, N, use_smem, nbb1,
                             vis, seq, rnd, p01s, n2s);
            }
        }
        __syncthreads();
    }

    // ── Walk tail (all rnd published; ~7 iterations) ──
    if (warp == 1 && valid)
        walk_advance(st, 0x40000000, L, lane, wid1, N, use_smem, nbb1,
                     vis, seq, rnd, p01s, n2s);
    __syncthreads();

    // ── Gather + recenter with all 8 warps (coalesced, latency-hidden) ──
    const int rows = 32 * (L + 1);
    for (int r = tid; r < rows; r += THREADS) {
        const int w   = r / (L + 1);
        const int pos = r - w * (L + 1);
        const int wg  = blk0 + w;
        if (wg < walks) {
            const int bb = wg / G;
            const float* __restrict__ xb = xyz + (long long)bb * N * 3;
            const int node = seq[pos * 32 + w];
            const long long o = ((long long)wg * (L + 1) + pos) * 3;
            out[o]     = __ldg(xb + 3 * node)     - cxyz[w * 3];
            out[o + 1] = __ldg(xb + 3 * node + 1) - cxyz[w * 3 + 1];
            out[o + 2] = __ldg(xb + 3 * node + 2) - cxyz[w * 3 + 2];
        }
    }
}

extern "C" void kernel_launch(void* const* d_in, const int* in_sizes, int n_in,
                              void* d_out, int out_size) {
    const float* xyz     = (const float*)d_in[0];
    const int*   nbrs    = (const int*)d_in[1];
    const int*   centers = (const int*)d_in[2];
    const int*   pN      = (const int*)d_in[3];

    const int walks = in_sizes[2];                  // B*G
    const int L = out_size / (walks * 3) - 1;       // seq_len

    cudaFuncSetAttribute(fused_walk_kernel,
                         cudaFuncAttributeMaxDynamicSharedMemorySize, SMEM_BYTES);

    const int blocks = (walks + 31) / 32;
    fused_walk_kernel<<<blocks, THREADS, SMEM_BYTES>>>(
        xyz, nbrs, centers, pN, (float*)d_out, in_sizes[0], walks, L);
}